// round 11
// baseline (speedup 1.0000x reference)
#include <cuda_runtime.h>
#include <cuda_bf16.h>

#define BATCH 256
#define NRET  100      // stored retrieval slots per row
#define RNUM  80       // RETRIEVAL_NUM actually used
#define DIM   768
#define DF4   (DIM / 4)   // 192 float4 per feature row
#define THRESH 0.5f

#define SLOTS_PER_WARP 2
#define GROUPS (RNUM / SLOTS_PER_WARP)      // 40 groups per batch row
#define WARPS_PER_BLOCK 8                   // 256 threads (R6 proven shape)
#define TOTAL_WARPS (BATCH * GROUPS)        // 10240
#define NBLOCKS (TOTAL_WARPS / WARPS_PER_BLOCK)  // 1280

// Output layout (concatenation, all f32 row-major):
//   vis_packed [B,80,768] | txt_packed [B,80,768] |
//   text_mask [B,81] | img_mask [B,81] | rr_mod [B,80] | labels [B,80]

__global__ __launch_bounds__(32 * WARPS_PER_BLOCK)
void rrcp_fused_kernel(const float* __restrict__ vis,
                       const float* __restrict__ txt,
                       const float* __restrict__ labels,
                       const float* __restrict__ rr,
                       float* __restrict__ out)
{
    const int w    = blockIdx.x * WARPS_PER_BLOCK + (threadIdx.x >> 5);
    const int lane = threadIdx.x & 31;
    const int b    = w / GROUPS;
    const int grp  = w % GROUPS;
    const int j0   = grp * SLOTS_PER_WARP;

    // ---- warp-local stable compaction scan over the 80 rr flags ----
    // (R6 structure: ballot + match-ballot + shfl; measured best.
    //  mge ballots removed from this hot path.)
    const float* __restrict__ rrow = rr + (size_t)b * NRET;
    int base = 0;
    int s0 = -1, s1 = -1;
    #pragma unroll
    for (int chunk = 0; chunk < 3; chunk++) {
        const int i = chunk * 32 + lane;
        const float v = (i < RNUM) ? __ldg(&rrow[i]) : 0.0f;
        const bool f = (i < RNUM) && (v > THRESH);
        const unsigned m = __ballot_sync(0xffffffffu, f);
        const int pos = base + __popc(m & ((1u << lane) - 1u));
        const unsigned m0 = __ballot_sync(0xffffffffu, f && pos == j0);
        const unsigned m1 = __ballot_sync(0xffffffffu, f && pos == j0 + 1);
        if (m0) s0 = __shfl_sync(0xffffffffu, i, __ffs(m0) - 1);
        if (m1) s1 = __shfl_sync(0xffffffffu, i, __ffs(m1) - 1);
        base += __popc(m);
    }
    const int cnt = base;   // uniform across warp

    // ---- streaming copy: 2 packed slots, per-tensor pipelined ----
    const float4* __restrict__ vbase =
        reinterpret_cast<const float4*>(vis) + (size_t)b * NRET * DF4;
    const float4* __restrict__ tbase =
        reinterpret_cast<const float4*>(txt) + (size_t)b * NRET * DF4;
    float4* __restrict__ ov = reinterpret_cast<float4*>(out)
                              + ((size_t)b * RNUM + j0) * DF4;
    float4* __restrict__ ot = ov + (size_t)BATCH * RNUM * DF4;

    const int srcs[SLOTS_PER_WARP] = { s0, s1 };
    #pragma unroll
    for (int k = 0; k < SLOTS_PER_WARP; k++) {
        const int src = srcs[k];
        float4* __restrict__ dv = ov + (size_t)k * DF4;
        float4* __restrict__ dt = ot + (size_t)k * DF4;
        if (src >= 0) {
            const float4* __restrict__ sv = vbase + (size_t)src * DF4;
            const float4* __restrict__ st = tbase + (size_t)src * DF4;
            float4 buf[6];
            #pragma unroll
            for (int u = 0; u < 6; u++) buf[u] = __ldg(&sv[lane + u * 32]);
            #pragma unroll
            for (int u = 0; u < 6; u++) __stcs(&dv[lane + u * 32], buf[u]);
            #pragma unroll
            for (int u = 0; u < 6; u++) buf[u] = __ldg(&st[lane + u * 32]);
            #pragma unroll
            for (int u = 0; u < 6; u++) __stcs(&dt[lane + u * 32], buf[u]);
        } else {
            const float4 z = make_float4(0.f, 0.f, 0.f, 0.f);
            #pragma unroll
            for (int u = 0; u < 6; u++) __stcs(&dv[lane + u * 32], z);
            #pragma unroll
            for (int u = 0; u < 6; u++) __stcs(&dt[lane + u * 32], z);
        }
    }

    // ---- small outputs: split across grp 0 (masks + rr_mod) and grp 1 (labels) ----
    if (grp == 0) {
        float* __restrict__ text_mask = out + 2 * (size_t)BATCH * RNUM * DIM;
        float* __restrict__ img_mask  = text_mask + (size_t)BATCH * (RNUM + 1);
        float* __restrict__ rr_mod    = img_mask  + (size_t)BATCH * (RNUM + 1);

        #pragma unroll
        for (int i = lane; i <= RNUM; i += 32) {
            const float m = (i <= cnt) ? 1.0f : 0.0f;
            text_mask[b * (RNUM + 1) + i] = m;
            img_mask [b * (RNUM + 1) + i] = (b == BATCH - 1) ? m : 1.0f;
        }

        // anyge: any rr[b, i] >= 0.5 over i in [0,80)  (only needed here)
        const float v0 = __ldg(&rrow[lane]);
        const float v1 = __ldg(&rrow[32 + lane]);
        const float v2 = (64 + lane < RNUM) ? __ldg(&rrow[64 + lane]) : 0.0f;
        const bool ge = (v0 >= THRESH) || (v1 >= THRESH) || (v2 >= THRESH);
        const unsigned anyge = __ballot_sync(0xffffffffu, ge);

        #pragma unroll
        for (int i = lane; i < RNUM; i += 32) {
            const float v = __ldg(&rrow[i]);
            float m = (v < THRESH) ? 0.0f : v;      // where(rr<0.5, 0, rr)
            if (i == 0 && anyge == 0u) m = 1.0f;    // all-zero row fix at col 0
            rr_mod[b * RNUM + i] = m;
        }
    } else if (grp == 1) {
        float* __restrict__ lab_out = out + 2 * (size_t)BATCH * RNUM * DIM
                                      + 2 * (size_t)BATCH * (RNUM + 1)
                                      + (size_t)BATCH * RNUM;
        #pragma unroll
        for (int i = lane; i < RNUM; i += 32)
            lab_out[b * RNUM + i] = __ldg(&labels[(size_t)b * NRET + i]);
    }
}

extern "C" void kernel_launch(void* const* d_in, const int* in_sizes, int n_in,
                              void* d_out, int out_size)
{
    // metadata order:
    // 0: mean_pooling_vec (unused)
    // 1: merge_text_vec   (unused)
    // 2: retrieved_visual_feature_embedding_cls [B,100,1,768]
    // 3: retrieved_textual_feature_embedding    [B,100,1,768]
    // 4: retrieved_label_list [B,100]
    // 5: RRCP                 [B,100]
    const float* vis    = (const float*)d_in[2];
    const float* txt    = (const float*)d_in[3];
    const float* labels = (const float*)d_in[4];
    const float* rr     = (const float*)d_in[5];
    float* out = (float*)d_out;

    rrcp_fused_kernel<<<NBLOCKS, 32 * WARPS_PER_BLOCK>>>(vis, txt, labels, rr, out);
}

// round 12
// speedup vs baseline: 1.0258x; 1.0258x over previous
#include <cuda_runtime.h>
#include <cuda_bf16.h>

#define BATCH 256
#define NRET  100      // stored retrieval slots per row
#define RNUM  80       // RETRIEVAL_NUM actually used
#define DIM   768
#define DF4   (DIM / 4)   // 192 float4 per feature row
#define THRESH 0.5f

#define SLOTS_PER_WARP 2
#define GROUPS (RNUM / SLOTS_PER_WARP)      // 40 groups per batch row
#define WARPS_PER_BLOCK 2                   // 64 threads: small blocks, deep residency
#define TOTAL_WARPS (BATCH * GROUPS)        // 10240
#define NBLOCKS (TOTAL_WARPS / WARPS_PER_BLOCK)  // 5120

// Output layout (concatenation, all f32 row-major):
//   vis_packed [B,80,768] | txt_packed [B,80,768] |
//   text_mask [B,81] | img_mask [B,81] | rr_mod [B,80] | labels [B,80]

__global__ __launch_bounds__(32 * WARPS_PER_BLOCK)
void rrcp_fused_kernel(const float* __restrict__ vis,
                       const float* __restrict__ txt,
                       const float* __restrict__ labels,
                       const float* __restrict__ rr,
                       float* __restrict__ out)
{
    const int w    = blockIdx.x * WARPS_PER_BLOCK + (threadIdx.x >> 5);
    const int lane = threadIdx.x & 31;
    const int b    = w / GROUPS;
    const int grp  = w % GROUPS;
    const int j0   = grp * SLOTS_PER_WARP;

    // ---- warp-local stable compaction scan over the 80 rr flags ----
    // (R6 structure: ballot + match-ballot + shfl; measured best)
    const float* __restrict__ rrow = rr + (size_t)b * NRET;
    int base = 0;
    int s0 = -1, s1 = -1;
    #pragma unroll
    for (int chunk = 0; chunk < 3; chunk++) {
        const int i = chunk * 32 + lane;
        const float v = (i < RNUM) ? __ldg(&rrow[i]) : 0.0f;
        const bool f = (i < RNUM) && (v > THRESH);
        const unsigned m = __ballot_sync(0xffffffffu, f);
        const int pos = base + __popc(m & ((1u << lane) - 1u));
        const unsigned m0 = __ballot_sync(0xffffffffu, f && pos == j0);
        const unsigned m1 = __ballot_sync(0xffffffffu, f && pos == j0 + 1);
        if (m0) s0 = __shfl_sync(0xffffffffu, i, __ffs(m0) - 1);
        if (m1) s1 = __shfl_sync(0xffffffffu, i, __ffs(m1) - 1);
        base += __popc(m);
    }
    const int cnt = base;   // uniform across warp

    // ---- streaming copy: 2 packed slots, per-tensor pipelined ----
    const float4* __restrict__ vbase =
        reinterpret_cast<const float4*>(vis) + (size_t)b * NRET * DF4;
    const float4* __restrict__ tbase =
        reinterpret_cast<const float4*>(txt) + (size_t)b * NRET * DF4;
    float4* __restrict__ ov = reinterpret_cast<float4*>(out)
                              + ((size_t)b * RNUM + j0) * DF4;
    float4* __restrict__ ot = ov + (size_t)BATCH * RNUM * DF4;

    const int srcs[SLOTS_PER_WARP] = { s0, s1 };
    #pragma unroll
    for (int k = 0; k < SLOTS_PER_WARP; k++) {
        const int src = srcs[k];
        float4* __restrict__ dv = ov + (size_t)k * DF4;
        float4* __restrict__ dt = ot + (size_t)k * DF4;
        if (src >= 0) {
            const float4* __restrict__ sv = vbase + (size_t)src * DF4;
            const float4* __restrict__ st = tbase + (size_t)src * DF4;
            float4 buf[6];
            #pragma unroll
            for (int u = 0; u < 6; u++) buf[u] = __ldg(&sv[lane + u * 32]);
            #pragma unroll
            for (int u = 0; u < 6; u++) __stcs(&dv[lane + u * 32], buf[u]);
            #pragma unroll
            for (int u = 0; u < 6; u++) buf[u] = __ldg(&st[lane + u * 32]);
            #pragma unroll
            for (int u = 0; u < 6; u++) __stcs(&dt[lane + u * 32], buf[u]);
        } else {
            const float4 z = make_float4(0.f, 0.f, 0.f, 0.f);
            #pragma unroll
            for (int u = 0; u < 6; u++) __stcs(&dv[lane + u * 32], z);
            #pragma unroll
            for (int u = 0; u < 6; u++) __stcs(&dt[lane + u * 32], z);
        }
    }

    // ---- small outputs: grp 0 (masks + rr_mod), grp 1 (labels) ----
    if (grp == 0) {
        float* __restrict__ text_mask = out + 2 * (size_t)BATCH * RNUM * DIM;
        float* __restrict__ img_mask  = text_mask + (size_t)BATCH * (RNUM + 1);
        float* __restrict__ rr_mod    = img_mask  + (size_t)BATCH * (RNUM + 1);

        #pragma unroll
        for (int i = lane; i <= RNUM; i += 32) {
            const float m = (i <= cnt) ? 1.0f : 0.0f;
            text_mask[b * (RNUM + 1) + i] = m;
            img_mask [b * (RNUM + 1) + i] = (b == BATCH - 1) ? m : 1.0f;
        }

        // anyge: any rr[b, i] >= 0.5 over i in [0,80)  (only needed here)
        const float v0 = __ldg(&rrow[lane]);
        const float v1 = __ldg(&rrow[32 + lane]);
        const float v2 = (64 + lane < RNUM) ? __ldg(&rrow[64 + lane]) : 0.0f;
        const bool ge = (v0 >= THRESH) || (v1 >= THRESH) || (v2 >= THRESH);
        const unsigned anyge = __ballot_sync(0xffffffffu, ge);

        #pragma unroll
        for (int i = lane; i < RNUM; i += 32) {
            const float v = __ldg(&rrow[i]);
            float m = (v < THRESH) ? 0.0f : v;      // where(rr<0.5, 0, rr)
            if (i == 0 && anyge == 0u) m = 1.0f;    // all-zero row fix at col 0
            rr_mod[b * RNUM + i] = m;
        }
    } else if (grp == 1) {
        float* __restrict__ lab_out = out + 2 * (size_t)BATCH * RNUM * DIM
                                      + 2 * (size_t)BATCH * (RNUM + 1)
                                      + (size_t)BATCH * RNUM;
        #pragma unroll
        for (int i = lane; i < RNUM; i += 32)
            lab_out[b * RNUM + i] = __ldg(&labels[(size_t)b * NRET + i]);
    }
}

extern "C" void kernel_launch(void* const* d_in, const int* in_sizes, int n_in,
                              void* d_out, int out_size)
{
    // metadata order:
    // 0: mean_pooling_vec (unused)
    // 1: merge_text_vec   (unused)
    // 2: retrieved_visual_feature_embedding_cls [B,100,1,768]
    // 3: retrieved_textual_feature_embedding    [B,100,1,768]
    // 4: retrieved_label_list [B,100]
    // 5: RRCP                 [B,100]
    const float* vis    = (const float*)d_in[2];
    const float* txt    = (const float*)d_in[3];
    const float* labels = (const float*)d_in[4];
    const float* rr     = (const float*)d_in[5];
    float* out = (float*)d_out;

    rrcp_fused_kernel<<<NBLOCKS, 32 * WARPS_PER_BLOCK>>>(vis, txt, labels, rr, out);
}

// round 14
// speedup vs baseline: 1.0462x; 1.0199x over previous
#include <cuda_runtime.h>
#include <cuda_bf16.h>

#define BATCH 256
#define NRET  100      // stored retrieval slots per row
#define RNUM  80       // RETRIEVAL_NUM actually used
#define DIM   768
#define DF8   (DIM / 8)   // 96 float8 (32B) chunks per feature row
#define THRESH 0.5f

#define SLOTS_PER_WARP 2
#define GROUPS (RNUM / SLOTS_PER_WARP)      // 40 groups per batch row
#define WARPS_PER_BLOCK 2                   // 64 threads (R12: best fused kernel)
#define TOTAL_WARPS (BATCH * GROUPS)        // 10240
#define NBLOCKS (TOTAL_WARPS / WARPS_PER_BLOCK)  // 5120

// 256-bit global memory ops (sm_100+): LDG.256 / STG.256
__device__ __forceinline__ void ldg256(const float* p, float4& a, float4& b) {
    asm volatile("ld.global.nc.v8.f32 {%0,%1,%2,%3,%4,%5,%6,%7}, [%8];"
                 : "=f"(a.x), "=f"(a.y), "=f"(a.z), "=f"(a.w),
                   "=f"(b.x), "=f"(b.y), "=f"(b.z), "=f"(b.w)
                 : "l"(p));
}
__device__ __forceinline__ void stg256cs(float* p, const float4& a, const float4& b) {
    asm volatile("st.global.cs.v8.f32 [%0], {%1,%2,%3,%4,%5,%6,%7,%8};"
                 :: "l"(p),
                    "f"(a.x), "f"(a.y), "f"(a.z), "f"(a.w),
                    "f"(b.x), "f"(b.y), "f"(b.z), "f"(b.w)
                 : "memory");
}

// Output layout (concatenation, all f32 row-major):
//   vis_packed [B,80,768] | txt_packed [B,80,768] |
//   text_mask [B,81] | img_mask [B,81] | rr_mod [B,80] | labels [B,80]

__global__ __launch_bounds__(32 * WARPS_PER_BLOCK)
void rrcp_fused_kernel(const float* __restrict__ vis,
                       const float* __restrict__ txt,
                       const float* __restrict__ labels,
                       const float* __restrict__ rr,
                       float* __restrict__ out)
{
    const int w    = blockIdx.x * WARPS_PER_BLOCK + (threadIdx.x >> 5);
    const int lane = threadIdx.x & 31;
    const int b    = w / GROUPS;
    const int grp  = w % GROUPS;
    const int j0   = grp * SLOTS_PER_WARP;

    // ---- warp-local stable compaction scan over the 80 rr flags ----
    const float* __restrict__ rrow = rr + (size_t)b * NRET;
    int base = 0;
    int s0 = -1, s1 = -1;
    #pragma unroll
    for (int chunk = 0; chunk < 3; chunk++) {
        const int i = chunk * 32 + lane;
        const float v = (i < RNUM) ? __ldg(&rrow[i]) : 0.0f;
        const bool f = (i < RNUM) && (v > THRESH);
        const unsigned m = __ballot_sync(0xffffffffu, f);
        const int pos = base + __popc(m & ((1u << lane) - 1u));
        const unsigned m0 = __ballot_sync(0xffffffffu, f && pos == j0);
        const unsigned m1 = __ballot_sync(0xffffffffu, f && pos == j0 + 1);
        if (m0) s0 = __shfl_sync(0xffffffffu, i, __ffs(m0) - 1);
        if (m1) s1 = __shfl_sync(0xffffffffu, i, __ffs(m1) - 1);
        base += __popc(m);
    }
    const int cnt = base;   // uniform across warp

    // ---- streaming copy: 2 packed slots, 256-bit ld/st, 3 chunks/lane/tensor ----
    const float* __restrict__ vbase = vis + (size_t)b * NRET * DIM;
    const float* __restrict__ tbase = txt + (size_t)b * NRET * DIM;
    float* __restrict__ ov = out + ((size_t)b * RNUM + j0) * DIM;
    float* __restrict__ ot = ov + (size_t)BATCH * RNUM * DIM;

    const int srcs[SLOTS_PER_WARP] = { s0, s1 };
    #pragma unroll
    for (int k = 0; k < SLOTS_PER_WARP; k++) {
        const int src = srcs[k];
        float* __restrict__ dv = ov + (size_t)k * DIM;
        float* __restrict__ dt = ot + (size_t)k * DIM;
        if (src >= 0) {
            const float* __restrict__ sv = vbase + (size_t)src * DIM;
            const float* __restrict__ st = tbase + (size_t)src * DIM;
            float4 a[3], c[3];
            #pragma unroll
            for (int u = 0; u < 3; u++)
                ldg256(sv + (lane + u * 32) * 8, a[u], c[u]);
            #pragma unroll
            for (int u = 0; u < 3; u++)
                stg256cs(dv + (lane + u * 32) * 8, a[u], c[u]);
            #pragma unroll
            for (int u = 0; u < 3; u++)
                ldg256(st + (lane + u * 32) * 8, a[u], c[u]);
            #pragma unroll
            for (int u = 0; u < 3; u++)
                stg256cs(dt + (lane + u * 32) * 8, a[u], c[u]);
        } else {
            const float4 z = make_float4(0.f, 0.f, 0.f, 0.f);
            #pragma unroll
            for (int u = 0; u < 3; u++)
                stg256cs(dv + (lane + u * 32) * 8, z, z);
            #pragma unroll
            for (int u = 0; u < 3; u++)
                stg256cs(dt + (lane + u * 32) * 8, z, z);
        }
    }

    // ---- small outputs: grp 0 (masks + rr_mod), grp 1 (labels) ----
    if (grp == 0) {
        float* __restrict__ text_mask = out + 2 * (size_t)BATCH * RNUM * DIM;
        float* __restrict__ img_mask  = text_mask + (size_t)BATCH * (RNUM + 1);
        float* __restrict__ rr_mod    = img_mask  + (size_t)BATCH * (RNUM + 1);

        #pragma unroll
        for (int i = lane; i <= RNUM; i += 32) {
            const float m = (i <= cnt) ? 1.0f : 0.0f;
            text_mask[b * (RNUM + 1) + i] = m;
            img_mask [b * (RNUM + 1) + i] = (b == BATCH - 1) ? m : 1.0f;
        }

        // anyge: any rr[b, i] >= 0.5 over i in [0,80)
        const float v0 = __ldg(&rrow[lane]);
        const float v1 = __ldg(&rrow[32 + lane]);
        const float v2 = (64 + lane < RNUM) ? __ldg(&rrow[64 + lane]) : 0.0f;
        const bool ge = (v0 >= THRESH) || (v1 >= THRESH) || (v2 >= THRESH);
        const unsigned anyge = __ballot_sync(0xffffffffu, ge);

        #pragma unroll
        for (int i = lane; i < RNUM; i += 32) {
            const float v = __ldg(&rrow[i]);
            float m = (v < THRESH) ? 0.0f : v;      // where(rr<0.5, 0, rr)
            if (i == 0 && anyge == 0u) m = 1.0f;    // all-zero row fix at col 0
            rr_mod[b * RNUM + i] = m;
        }
    } else if (grp == 1) {
        float* __restrict__ lab_out = out + 2 * (size_t)BATCH * RNUM * DIM
                                      + 2 * (size_t)BATCH * (RNUM + 1)
                                      + (size_t)BATCH * RNUM;
        #pragma unroll
        for (int i = lane; i < RNUM; i += 32)
            lab_out[b * RNUM + i] = __ldg(&labels[(size_t)b * NRET + i]);
    }
}

extern "C" void kernel_launch(void* const* d_in, const int* in_sizes, int n_in,
                              void* d_out, int out_size)
{
    // metadata order:
    // 0: mean_pooling_vec (unused)
    // 1: merge_text_vec   (unused)
    // 2: retrieved_visual_feature_embedding_cls [B,100,1,768]
    // 3: retrieved_textual_feature_embedding    [B,100,1,768]
    // 4: retrieved_label_list [B,100]
    // 5: RRCP                 [B,100]
    const float* vis    = (const float*)d_in[2];
    const float* txt    = (const float*)d_in[3];
    const float* labels = (const float*)d_in[4];
    const float* rr     = (const float*)d_in[5];
    float* out = (float*)d_out;

    rrcp_fused_kernel<<<NBLOCKS, 32 * WARPS_PER_BLOCK>>>(vis, txt, labels, rr, out);
}